// round 1
// baseline (speedup 1.0000x reference)
#include <cuda_runtime.h>
#include <cuda_bf16.h>
#include <math.h>

// ---------------- problem constants ----------------
#define NMAX 100000
#define EMAX 1200000

// ---------------- device scratch (no cudaMalloc allowed) ----------------
__device__ float d_XC[(size_t)NMAX * 256];    // [h0(128) | h1(64) | h2(64)] per node
__device__ float d_agg[(size_t)NMAX * 128];   // aggregation output
__device__ float d_tbuf[(size_t)NMAX * 128];  // MLP hidden
__device__ float d_ybuf[(size_t)NMAX * 64];   // pre-BN output
__device__ int   d_cnt[NMAX];
__device__ int   d_cursor[NMAX];
__device__ int   d_rowstart[NMAX + 1];
__device__ int   d_col[EMAX];
__device__ int   d_bsum[256];
__device__ int   d_boff[256];
__device__ float d_sum[3 * 64];
__device__ float d_sq[3 * 64];
__device__ float d_sc[3 * 64];
__device__ float d_sh[3 * 64];

__device__ __forceinline__ float lrelu(float x) { return x > 0.f ? x : 0.01f * x; }

// ---------------- init: zero counters + stats ----------------
__global__ void zero_kernel(int n) {
    int i = blockIdx.x * blockDim.x + threadIdx.x;
    if (i < n) { d_cnt[i] = 0; d_cursor[i] = 0; }
    if (i < 192) { d_sum[i] = 0.f; d_sq[i] = 0.f; }
}

// ---------------- embedding concat -> h0 (XC cols 0..127) ----------------
__global__ void embed_kernel(const int* __restrict__ deg, const int* __restrict__ lab,
                             const float* __restrict__ emb_deg,
                             const float* __restrict__ emb_lab, int n) {
    int idx = blockIdx.x * blockDim.x + threadIdx.x;
    int i = idx >> 5, c = idx & 31;       // 32 float4 chunks = 128 floats
    if (i >= n) return;
    float4 v;
    if (c < 16) v = ((const float4*)emb_deg)[(size_t)deg[i] * 16 + c];
    else        v = ((const float4*)emb_lab)[(size_t)lab[i] * 16 + (c - 16)];
    ((float4*)d_XC)[(size_t)i * 64 + c] = v;
}

// ---------------- CSR build ----------------
__global__ void count_kernel(const int* __restrict__ edge, int e) {
    int i = blockIdx.x * blockDim.x + threadIdx.x;
    if (i < e) atomicAdd(&d_cnt[edge[e + i]], 1);
}

__global__ void scanA_kernel(int n) {
    __shared__ int wsum[32];
    int t = threadIdx.x;
    int idx = blockIdx.x * 1024 + t;
    int v = (idx < n) ? d_cnt[idx] : 0;
    #pragma unroll
    for (int o = 16; o; o >>= 1) v += __shfl_xor_sync(0xffffffffu, v, o);
    if ((t & 31) == 0) wsum[t >> 5] = v;
    __syncthreads();
    if (t < 32) {
        int s = wsum[t];
        #pragma unroll
        for (int o = 16; o; o >>= 1) s += __shfl_xor_sync(0xffffffffu, s, o);
        if (t == 0) d_bsum[blockIdx.x] = s;
    }
}

__global__ void scanB_kernel(int nb, int n) {
    if (threadIdx.x == 0 && blockIdx.x == 0) {
        int run = 0;
        for (int b = 0; b < nb; b++) { d_boff[b] = run; run += d_bsum[b]; }
        d_rowstart[n] = run;
    }
}

__global__ void scanC_kernel(int n) {
    __shared__ int wsum[32];
    int t = threadIdx.x;
    int idx = blockIdx.x * 1024 + t;
    int v = (idx < n) ? d_cnt[idx] : 0;
    int lane = t & 31, wid = t >> 5;
    int inc = v;
    #pragma unroll
    for (int o = 1; o < 32; o <<= 1) {
        int u = __shfl_up_sync(0xffffffffu, inc, o);
        if (lane >= o) inc += u;
    }
    if (lane == 31) wsum[wid] = inc;
    __syncthreads();
    if (t < 32) {
        int s = wsum[t];
        int sInc = s;
        #pragma unroll
        for (int o = 1; o < 32; o <<= 1) {
            int u = __shfl_up_sync(0xffffffffu, sInc, o);
            if (t >= o) sInc += u;
        }
        wsum[t] = sInc - s;  // exclusive warp offsets
    }
    __syncthreads();
    if (idx < n) d_rowstart[idx] = d_boff[blockIdx.x] + wsum[wid] + inc - v;
}

__global__ void fill_kernel(const int* __restrict__ edge, int e) {
    int i = blockIdx.x * blockDim.x + threadIdx.x;
    if (i < e) {
        int d = edge[e + i];
        int p = atomicAdd(&d_cursor[d], 1);
        d_col[d_rowstart[d] + p] = edge[i];
    }
}

// ---------------- GIN aggregation: agg[i] = (1+eps)*h[i] + sum_nbr h[nbr] ----------------
template <int D>   // floats per feature row (128 or 64)
__global__ void gather_kernel(const float* __restrict__ hsrc, int ldh,
                              float* __restrict__ aggout, int lda,
                              const float* __restrict__ epsp, int n) {
    constexpr int C = D / 4;        // float4 chunks per node
    constexpr int NPW = 32 / C;     // nodes per warp
    int lane = threadIdx.x & 31;
    int warp = (blockIdx.x * blockDim.x + threadIdx.x) >> 5;
    int sub = lane / C;
    int c = lane % C;
    int i = warp * NPW + sub;
    if (i >= n) return;
    float e1 = 1.0f + epsp[0];
    const float4* hb = (const float4*)hsrc;
    int ldh4 = ldh >> 2;
    float4 a = hb[(size_t)i * ldh4 + c];
    float4 s = make_float4(a.x * e1, a.y * e1, a.z * e1, a.w * e1);
    int js = d_rowstart[i], je = d_rowstart[i + 1];
    for (int j = js; j < je; j++) {
        int nb = d_col[j];
        float4 v = hb[(size_t)nb * ldh4 + c];
        s.x += v.x; s.y += v.y; s.z += v.z; s.w += v.w;
    }
    ((float4*)aggout)[(size_t)i * (lda >> 2) + c] = s;
}

// ---------------- register-tiled fp32 GEMM: y[n,H] = act(x[n,K] @ w[K,H] + b) ----------------
template <int K, int H, bool ACT, bool STATS>
__global__ void __launch_bounds__(256)
gemm_kernel(const float* __restrict__ x, int ldx,
            const float* __restrict__ w, const float* __restrict__ bias,
            float* __restrict__ y, int ldy,
            float* __restrict__ gsum, float* __restrict__ gsq, int n) {
    constexpr int NT = 64;
    constexpr int KC = 32;
    constexpr int OG = H / 8;             // out groups of 8
    constexpr int NPT = NT * OG / 256;    // nodes per thread

    __shared__ __align__(16) float xs[NT][KC + 1];
    __shared__ __align__(16) float ws[KC][H];
    __shared__ float colsum[H];
    __shared__ float colsq[H];

    const int t = threadIdx.x;
    const int og = t % OG;
    const int ng = t / OG;
    const int node0 = blockIdx.x * NT;

    float acc[NPT][8];
    #pragma unroll
    for (int i = 0; i < NPT; i++)
        #pragma unroll
        for (int j = 0; j < 8; j++) acc[i][j] = 0.f;

    for (int k0 = 0; k0 < K; k0 += KC) {
        // load x tile (64 nodes x 32 k)
        {
            int nl = t >> 2;
            int kb = (t & 3) * 8;
            int gn = node0 + nl;
            float4 a, b;
            if (gn < n) {
                const float4* xr = (const float4*)(x + (size_t)gn * ldx + k0 + kb);
                a = xr[0]; b = xr[1];
            } else {
                a = make_float4(0.f, 0.f, 0.f, 0.f); b = a;
            }
            xs[nl][kb + 0] = a.x; xs[nl][kb + 1] = a.y;
            xs[nl][kb + 2] = a.z; xs[nl][kb + 3] = a.w;
            xs[nl][kb + 4] = b.x; xs[nl][kb + 5] = b.y;
            xs[nl][kb + 6] = b.z; xs[nl][kb + 7] = b.w;
        }
        // load w chunk (32 x H, contiguous rows)
        {
            const float4* wsrc = (const float4*)(w + (size_t)k0 * H);
            float4* wdst = (float4*)(&ws[0][0]);
            #pragma unroll
            for (int j = t; j < KC * H / 4; j += 256) wdst[j] = wsrc[j];
        }
        __syncthreads();
        #pragma unroll
        for (int k = 0; k < KC; k++) {
            float4 w0 = *(const float4*)(&ws[k][og * 8]);
            float4 w1v = *(const float4*)(&ws[k][og * 8 + 4]);
            #pragma unroll
            for (int i = 0; i < NPT; i++) {
                float xv = xs[ng * NPT + i][k];
                acc[i][0] += xv * w0.x;  acc[i][1] += xv * w0.y;
                acc[i][2] += xv * w0.z;  acc[i][3] += xv * w0.w;
                acc[i][4] += xv * w1v.x; acc[i][5] += xv * w1v.y;
                acc[i][6] += xv * w1v.z; acc[i][7] += xv * w1v.w;
            }
        }
        __syncthreads();
    }

    float bset[8];
    #pragma unroll
    for (int j = 0; j < 8; j++) bset[j] = bias[og * 8 + j];

    if (STATS) {
        if (t < H) { colsum[t] = 0.f; colsq[t] = 0.f; }
        __syncthreads();
    }

    #pragma unroll
    for (int i = 0; i < NPT; i++) {
        int gn = node0 + ng * NPT + i;
        if (gn < n) {
            float v[8];
            #pragma unroll
            for (int j = 0; j < 8; j++) {
                float z = acc[i][j] + bset[j];
                if (ACT) z = lrelu(z);
                v[j] = z;
            }
            float4* yr = (float4*)(y + (size_t)gn * ldy + og * 8);
            yr[0] = make_float4(v[0], v[1], v[2], v[3]);
            yr[1] = make_float4(v[4], v[5], v[6], v[7]);
            if (STATS) {
                #pragma unroll
                for (int j = 0; j < 8; j++) {
                    atomicAdd(&colsum[og * 8 + j], v[j]);
                    atomicAdd(&colsq[og * 8 + j], v[j] * v[j]);
                }
            }
        }
    }
    if (STATS) {
        __syncthreads();
        if (t < H) {
            atomicAdd(&gsum[t], colsum[t]);
            atomicAdd(&gsq[t], colsq[t]);
        }
    }
}

// ---------------- BN scale/shift from batch stats ----------------
__global__ void bnstat_kernel(const float* __restrict__ gsum, const float* __restrict__ gsq,
                              const float* __restrict__ g, const float* __restrict__ b,
                              float* __restrict__ sc, float* __restrict__ sh, int n) {
    int c = threadIdx.x;
    if (c < 64) {
        float invn = 1.0f / (float)n;
        float m = gsum[c] * invn;
        float v = gsq[c] * invn - m * m;
        float s = g[c] * rsqrtf(v + 1e-5f);
        sc[c] = s;
        sh[c] = b[c] - m * s;
    }
}

// ---------------- apply BN + lrelu -> h_next (strided into XC) ----------------
__global__ void bnapply_kernel(const float* __restrict__ y,
                               const float* __restrict__ sc, const float* __restrict__ sh,
                               float* __restrict__ out, int ldo, int off, int n) {
    int idx = blockIdx.x * blockDim.x + threadIdx.x;
    int i = idx >> 4, c = idx & 15;   // 16 float4 = 64 floats
    if (i >= n) return;
    float4 v = ((const float4*)y)[(size_t)i * 16 + c];
    float4 s4 = ((const float4*)sc)[c];
    float4 h4 = ((const float4*)sh)[c];
    v.x = lrelu(v.x * s4.x + h4.x);
    v.y = lrelu(v.y * s4.y + h4.y);
    v.z = lrelu(v.z * s4.z + h4.z);
    v.w = lrelu(v.w * s4.w + h4.w);
    ((float4*)(out + (size_t)i * ldo + off))[c] = v;
}

// ---------------- head: lrelu(bn(y)) @ fc_w2 + b2, sigmoid ----------------
__global__ void head_kernel(const float* __restrict__ y,
                            const float* __restrict__ sc, const float* __restrict__ sh,
                            const float* __restrict__ w2, const float* __restrict__ b2,
                            float* __restrict__ out, int n) {
    int lane = threadIdx.x & 31;
    int i = (blockIdx.x * blockDim.x + threadIdx.x) >> 5;
    if (i >= n) return;
    float2 v = ((const float2*)y)[(size_t)i * 32 + lane];
    float z0 = lrelu(v.x * sc[2 * lane] + sh[2 * lane]);
    float z1 = lrelu(v.y * sc[2 * lane + 1] + sh[2 * lane + 1]);
    float a = z0 * w2[2 * lane] + z1 * w2[2 * lane + 1];
    #pragma unroll
    for (int o = 16; o; o >>= 1) a += __shfl_xor_sync(0xffffffffu, a, o);
    if (lane == 0) out[i] = 1.0f / (1.0f + expf(-(a + b2[0])));
}

// ---------------- launch ----------------
extern "C" void kernel_launch(void* const* d_in, const int* in_sizes, int n_in,
                              void* d_out, int out_size) {
    const int*   node_deg = (const int*)d_in[0];
    const int*   node_lab = (const int*)d_in[1];
    const int*   edge     = (const int*)d_in[2];
    const float* emb_deg  = (const float*)d_in[3];
    const float* emb_lab  = (const float*)d_in[4];
    const float* l0_w1 = (const float*)d_in[5];
    const float* l0_b1 = (const float*)d_in[6];
    const float* l0_w2 = (const float*)d_in[7];
    const float* l0_b2 = (const float*)d_in[8];
    const float* l0_eps = (const float*)d_in[9];
    const float* bn0_g = (const float*)d_in[10];
    const float* bn0_b = (const float*)d_in[11];
    const float* l1_w1 = (const float*)d_in[12];
    const float* l1_b1 = (const float*)d_in[13];
    const float* l1_w2 = (const float*)d_in[14];
    const float* l1_b2 = (const float*)d_in[15];
    const float* l1_eps = (const float*)d_in[16];
    const float* bn1_g = (const float*)d_in[17];
    const float* bn1_b = (const float*)d_in[18];
    const float* fc_w1 = (const float*)d_in[19];
    const float* fc_b1 = (const float*)d_in[20];
    const float* fc_bn_g = (const float*)d_in[21];
    const float* fc_bn_b = (const float*)d_in[22];
    const float* fc_w2 = (const float*)d_in[23];
    const float* fc_b2 = (const float*)d_in[24];

    int n = in_sizes[0];
    int E = in_sizes[2] / 2;

    float *XC, *agg, *tbuf, *ybuf, *sumv, *sqv, *scv, *shv;
    cudaGetSymbolAddress((void**)&XC,   d_XC);
    cudaGetSymbolAddress((void**)&agg,  d_agg);
    cudaGetSymbolAddress((void**)&tbuf, d_tbuf);
    cudaGetSymbolAddress((void**)&ybuf, d_ybuf);
    cudaGetSymbolAddress((void**)&sumv, d_sum);
    cudaGetSymbolAddress((void**)&sqv,  d_sq);
    cudaGetSymbolAddress((void**)&scv,  d_sc);
    cudaGetSymbolAddress((void**)&shv,  d_sh);

    int NB = (n + 1023) / 1024;

    // init + embeddings + CSR build
    zero_kernel<<<(n + 255) / 256, 256>>>(n);
    embed_kernel<<<((size_t)n * 32 + 255) / 256, 256>>>(node_deg, node_lab, emb_deg, emb_lab, n);
    count_kernel<<<(E + 255) / 256, 256>>>(edge, E);
    scanA_kernel<<<NB, 1024>>>(n);
    scanB_kernel<<<1, 32>>>(NB, n);
    scanC_kernel<<<NB, 1024>>>(n);
    fill_kernel<<<(E + 255) / 256, 256>>>(edge, E);

    // ---- GIN layer 0: h0 (XC cols 0..127) ----
    gather_kernel<128><<<((size_t)n * 32 + 255) / 256, 256>>>(XC, 256, agg, 128, l0_eps, n);
    gemm_kernel<128, 128, true,  false><<<(n + 63) / 64, 256>>>(agg, 128, l0_w1, l0_b1, tbuf, 128, nullptr, nullptr, n);
    gemm_kernel<128,  64, false, true ><<<(n + 63) / 64, 256>>>(tbuf, 128, l0_w2, l0_b2, ybuf, 64, sumv + 0, sqv + 0, n);
    bnstat_kernel<<<1, 64>>>(sumv + 0, sqv + 0, bn0_g, bn0_b, scv + 0, shv + 0, n);
    bnapply_kernel<<<((size_t)n * 16 + 255) / 256, 256>>>(ybuf, scv + 0, shv + 0, XC, 256, 128, n);

    // ---- GIN layer 1: h1 (XC cols 128..191) ----
    gather_kernel<64><<<(((size_t)(n + 1) / 2) * 32 + 255) / 256, 256>>>(XC + 128, 256, agg, 64, l1_eps, n);
    gemm_kernel<64, 64, true,  false><<<(n + 63) / 64, 256>>>(agg, 64, l1_w1, l1_b1, tbuf, 64, nullptr, nullptr, n);
    gemm_kernel<64, 64, false, true ><<<(n + 63) / 64, 256>>>(tbuf, 64, l1_w2, l1_b2, ybuf, 64, sumv + 64, sqv + 64, n);
    bnstat_kernel<<<1, 64>>>(sumv + 64, sqv + 64, bn1_g, bn1_b, scv + 64, shv + 64, n);
    bnapply_kernel<<<((size_t)n * 16 + 255) / 256, 256>>>(ybuf, scv + 64, shv + 64, XC, 256, 192, n);

    // ---- head: concat(h0,h1,h2) @ fc_w1 -> BN -> lrelu -> fc_w2 -> sigmoid ----
    gemm_kernel<256, 64, false, true><<<(n + 63) / 64, 256>>>(XC, 256, fc_w1, fc_b1, ybuf, 64, sumv + 128, sqv + 128, n);
    bnstat_kernel<<<1, 64>>>(sumv + 128, sqv + 128, fc_bn_g, fc_bn_b, scv + 128, shv + 128, n);
    head_kernel<<<((size_t)n * 32 + 255) / 256, 256>>>(ybuf, scv + 128, shv + 128, fc_w2, fc_b2, (float*)d_out, n);
}

// round 2
// speedup vs baseline: 1.5525x; 1.5525x over previous
#include <cuda_runtime.h>
#include <cuda_bf16.h>
#include <math.h>

// ---------------- problem constants ----------------
#define NMAX 100000
#define EMAX 1200000

// ---------------- device scratch ----------------
__device__ float d_t0[(size_t)NMAX * 128];   // h0 @ l0_w1 per node
__device__ float d_XC[(size_t)NMAX * 128];   // [h1(64) | h2(64)]
__device__ float d_agg[(size_t)NMAX * 128];  // gather output / z1
__device__ float d_tbuf[(size_t)NMAX * 64];  // layer-1 hidden
__device__ float d_ybuf[(size_t)NMAX * 64];  // pre-BN output
__device__ float d_hb[(size_t)NMAX * 64];    // head per-node row bias (h0 part + fc_b1)
__device__ float d_Tdeg[65 * 128];
__device__ float d_Tlab[16 * 128];
__device__ float d_Fdeg[65 * 64];
__device__ float d_Flab[16 * 64];
__device__ int   d_cnt[NMAX];
__device__ int   d_cursor[NMAX];
__device__ int   d_rowstart[NMAX + 1];
__device__ int   d_col[EMAX];
__device__ int   d_bsum[256];
__device__ int   d_boff[256];
__device__ float d_sum[3 * 64];
__device__ float d_sq[3 * 64];

__device__ __forceinline__ float lrelu(float x) { return x > 0.f ? x : 0.01f * x; }

// ---------------- init ----------------
__global__ void zero_kernel(int n) {
    int i = blockIdx.x * blockDim.x + threadIdx.x;
    if (i < n) { d_cnt[i] = 0; d_cursor[i] = 0; }
    if (i < 192) { d_sum[i] = 0.f; d_sq[i] = 0.f; }
}

// ---------------- dictionary tables: emb @ weight-slices ----------------
__global__ void tables_kernel(const float* __restrict__ emb_deg,
                              const float* __restrict__ emb_lab,
                              const float* __restrict__ l0_w1,
                              const float* __restrict__ fc_w1) {
    __shared__ float e[64];
    int b = blockIdx.x, t = threadIdx.x;
    const float* erow; const float* w; float* out; int H;
    if (b < 65)       { erow = emb_deg + b * 64;         w = l0_w1;            out = d_Tdeg + b * 128;         H = 128; }
    else if (b < 81)  { erow = emb_lab + (b - 65) * 64;  w = l0_w1 + 64 * 128; out = d_Tlab + (b - 65) * 128;  H = 128; }
    else if (b < 146) { erow = emb_deg + (b - 81) * 64;  w = fc_w1;            out = d_Fdeg + (b - 81) * 64;   H = 64;  }
    else              { erow = emb_lab + (b - 146) * 64; w = fc_w1 + 64 * 64;  out = d_Flab + (b - 146) * 64;  H = 64;  }
    if (t < 64) e[t] = erow[t];
    __syncthreads();
    if (t < H) {
        float s = 0.f;
        #pragma unroll 8
        for (int k = 0; k < 64; k++) s += e[k] * w[k * H + t];
        out[t] = s;
    }
}

// ---------------- per-node lookups: t0 = Tdeg[deg]+Tlab[lab]; hb = Fdeg[deg]+Flab[lab]+fc_b1 ----------------
__global__ void t0hb_kernel(const int* __restrict__ deg, const int* __restrict__ lab,
                            const float* __restrict__ fc_b1, int n) {
    int idx = blockIdx.x * blockDim.x + threadIdx.x;
    int i = idx / 48, c = idx % 48;
    if (i >= n) return;
    int dg = deg[i], lb = lab[i];
    if (c < 32) {
        float4 a = ((const float4*)d_Tdeg)[dg * 32 + c];
        float4 b = ((const float4*)d_Tlab)[lb * 32 + c];
        ((float4*)d_t0)[(size_t)i * 32 + c] =
            make_float4(a.x + b.x, a.y + b.y, a.z + b.z, a.w + b.w);
    } else {
        c -= 32;
        float4 a = ((const float4*)d_Fdeg)[dg * 16 + c];
        float4 b = ((const float4*)d_Flab)[lb * 16 + c];
        float4 bb = ((const float4*)fc_b1)[c];
        ((float4*)d_hb)[(size_t)i * 16 + c] =
            make_float4(a.x + b.x + bb.x, a.y + b.y + bb.y, a.z + b.z + bb.z, a.w + b.w + bb.w);
    }
}

// ---------------- CSR build ----------------
__global__ void count_kernel(const int* __restrict__ edge, int e) {
    int i = blockIdx.x * blockDim.x + threadIdx.x;
    if (i < e) atomicAdd(&d_cnt[edge[e + i]], 1);
}

__global__ void scanA_kernel(int n) {
    __shared__ int wsum[32];
    int t = threadIdx.x;
    int idx = blockIdx.x * 1024 + t;
    int v = (idx < n) ? d_cnt[idx] : 0;
    #pragma unroll
    for (int o = 16; o; o >>= 1) v += __shfl_xor_sync(0xffffffffu, v, o);
    if ((t & 31) == 0) wsum[t >> 5] = v;
    __syncthreads();
    if (t < 32) {
        int s = wsum[t];
        #pragma unroll
        for (int o = 16; o; o >>= 1) s += __shfl_xor_sync(0xffffffffu, s, o);
        if (t == 0) d_bsum[blockIdx.x] = s;
    }
}

__global__ void scanB_kernel(int nb, int n) {
    if (threadIdx.x == 0 && blockIdx.x == 0) {
        int run = 0;
        for (int b = 0; b < nb; b++) { d_boff[b] = run; run += d_bsum[b]; }
        d_rowstart[n] = run;
    }
}

__global__ void scanC_kernel(int n) {
    __shared__ int wsum[32];
    int t = threadIdx.x;
    int idx = blockIdx.x * 1024 + t;
    int v = (idx < n) ? d_cnt[idx] : 0;
    int lane = t & 31, wid = t >> 5;
    int inc = v;
    #pragma unroll
    for (int o = 1; o < 32; o <<= 1) {
        int u = __shfl_up_sync(0xffffffffu, inc, o);
        if (lane >= o) inc += u;
    }
    if (lane == 31) wsum[wid] = inc;
    __syncthreads();
    if (t < 32) {
        int s = wsum[t];
        int sInc = s;
        #pragma unroll
        for (int o = 1; o < 32; o <<= 1) {
            int u = __shfl_up_sync(0xffffffffu, sInc, o);
            if (t >= o) sInc += u;
        }
        wsum[t] = sInc - s;
    }
    __syncthreads();
    if (idx < n) d_rowstart[idx] = d_boff[blockIdx.x] + wsum[wid] + inc - v;
}

__global__ void fill_kernel(const int* __restrict__ edge, int e) {
    int i = blockIdx.x * blockDim.x + threadIdx.x;
    if (i < e) {
        int d = edge[e + i];
        int p = atomicAdd(&d_cursor[d], 1);
        d_col[d_rowstart[d] + p] = edge[i];
    }
}

// ---------------- GIN aggregation (optionally fused bias+lrelu) ----------------
template <int D, bool ACT>
__global__ void gather_kernel(const float* __restrict__ hsrc, int ldh,
                              float* __restrict__ out, int ldo,
                              const float* __restrict__ epsp,
                              const float* __restrict__ bias, int n) {
    constexpr int C = D / 4;
    constexpr int NPW = 32 / C;
    int lane = threadIdx.x & 31;
    int warp = (blockIdx.x * blockDim.x + threadIdx.x) >> 5;
    int i = warp * NPW + lane / C;
    int c = lane % C;
    if (i >= n) return;
    float e1 = 1.0f + epsp[0];
    const float4* hb4 = (const float4*)hsrc;
    int ldh4 = ldh >> 2;
    float4 a = hb4[(size_t)i * ldh4 + c];
    float4 s = make_float4(a.x * e1, a.y * e1, a.z * e1, a.w * e1);
    int js = d_rowstart[i], je = d_rowstart[i + 1];
    for (int j = js; j < je; j++) {
        int nb = d_col[j];
        float4 v = hb4[(size_t)nb * ldh4 + c];
        s.x += v.x; s.y += v.y; s.z += v.z; s.w += v.w;
    }
    if (ACT) {
        float4 b4 = ((const float4*)bias)[c];
        s.x = lrelu(s.x + b4.x); s.y = lrelu(s.y + b4.y);
        s.z = lrelu(s.z + b4.z); s.w = lrelu(s.w + b4.w);
    }
    ((float4*)out)[(size_t)i * (ldo >> 2) + c] = s;
}

// ---------------- register-tiled fp32 GEMM: y[n,64] = act(x[n,K] @ w[K,64] + bias) ----------------
template <int K, bool ACT, bool STATS, bool RB>
__global__ void __launch_bounds__(256, 2)
gemm64_kernel(const float* __restrict__ x, int ldx,
              const float* __restrict__ w,
              const float* __restrict__ bias,
              const float* __restrict__ rowbias,
              float* __restrict__ y,
              float* __restrict__ gsum, float* __restrict__ gsq, int n) {
    constexpr int KC = 32;
    __shared__ float xs[128][33];
    __shared__ __align__(16) float ws[KC][64];
    __shared__ float csum[64], csq[64];

    const int t = threadIdx.x;
    const int og = t & 7;     // col group: cols og*8 .. og*8+7
    const int ng = t >> 3;    // node group: nodes ng*4 .. ng*4+3
    const int node0 = blockIdx.x * 128;

    float acc[4][8];
    #pragma unroll
    for (int i = 0; i < 4; i++)
        #pragma unroll
        for (int j = 0; j < 8; j++) acc[i][j] = 0.f;

    for (int k0 = 0; k0 < K; k0 += KC) {
        // x tile: 128 rows x 32 k; thread t loads row t>>1, 16 floats at (t&1)*16
        {
            int row = t >> 1;
            int cb = (t & 1) * 16;
            int gn = node0 + row;
            const float4* src = (const float4*)(x + (size_t)gn * ldx + k0 + cb);
            #pragma unroll
            for (int i = 0; i < 4; i++) {
                float4 v = (gn < n) ? src[i] : make_float4(0.f, 0.f, 0.f, 0.f);
                xs[row][cb + 4 * i + 0] = v.x;
                xs[row][cb + 4 * i + 1] = v.y;
                xs[row][cb + 4 * i + 2] = v.z;
                xs[row][cb + 4 * i + 3] = v.w;
            }
        }
        // w chunk: 32 x 64 = 512 float4; 2 per thread
        {
            const float4* wsrc = (const float4*)(w + (size_t)k0 * 64);
            float4* wdst = (float4*)(&ws[0][0]);
            wdst[t] = wsrc[t];
            wdst[t + 256] = wsrc[t + 256];
        }
        __syncthreads();
        #pragma unroll
        for (int k = 0; k < KC; k++) {
            float4 w0 = *(const float4*)(&ws[k][og * 8]);
            float4 w1v = *(const float4*)(&ws[k][og * 8 + 4]);
            float xv[4];
            #pragma unroll
            for (int i = 0; i < 4; i++) xv[i] = xs[ng * 4 + i][k];
            #pragma unroll
            for (int i = 0; i < 4; i++) {
                acc[i][0] += xv[i] * w0.x;  acc[i][1] += xv[i] * w0.y;
                acc[i][2] += xv[i] * w0.z;  acc[i][3] += xv[i] * w0.w;
                acc[i][4] += xv[i] * w1v.x; acc[i][5] += xv[i] * w1v.y;
                acc[i][6] += xv[i] * w1v.z; acc[i][7] += xv[i] * w1v.w;
            }
        }
        __syncthreads();
    }

    if (STATS) {
        if (t < 64) { csum[t] = 0.f; csq[t] = 0.f; }
        __syncthreads();
    }

    float b8[8];
    if (!RB) {
        #pragma unroll
        for (int j = 0; j < 8; j++) b8[j] = bias[og * 8 + j];
    }

    #pragma unroll
    for (int i = 0; i < 4; i++) {
        int gn = node0 + ng * 4 + i;
        if (gn < n) {
            float r[8];
            if (RB) {
                float4 r0 = ((const float4*)(rowbias + (size_t)gn * 64 + og * 8))[0];
                float4 r1 = ((const float4*)(rowbias + (size_t)gn * 64 + og * 8))[1];
                r[0] = r0.x; r[1] = r0.y; r[2] = r0.z; r[3] = r0.w;
                r[4] = r1.x; r[5] = r1.y; r[6] = r1.z; r[7] = r1.w;
            }
            float v[8];
            #pragma unroll
            for (int j = 0; j < 8; j++) {
                float z = acc[i][j] + (RB ? r[j] : b8[j]);
                if (ACT) z = lrelu(z);
                v[j] = z;
            }
            float4* yr = (float4*)(y + (size_t)gn * 64 + og * 8);
            yr[0] = make_float4(v[0], v[1], v[2], v[3]);
            yr[1] = make_float4(v[4], v[5], v[6], v[7]);
            if (STATS) {
                #pragma unroll
                for (int j = 0; j < 8; j++) {
                    atomicAdd(&csum[og * 8 + j], v[j]);
                    atomicAdd(&csq[og * 8 + j], v[j] * v[j]);
                }
            }
        }
    }
    if (STATS) {
        __syncthreads();
        if (t < 64) {
            atomicAdd(&gsum[t], csum[t]);
            atomicAdd(&gsq[t], csq[t]);
        }
    }
}

// ---------------- BN apply (stats->scale/shift fused) + lrelu ----------------
__global__ void bnapply_kernel(const float* __restrict__ y,
                               const float* __restrict__ gsum, const float* __restrict__ gsq,
                               const float* __restrict__ g, const float* __restrict__ b,
                               float* __restrict__ out, int ldo, int off, int n) {
    __shared__ float sc[64], sh[64];
    int t = threadIdx.x;
    if (t < 64) {
        float invn = 1.0f / (float)n;
        float m = gsum[t] * invn;
        float var = gsq[t] * invn - m * m;
        float s = g[t] * rsqrtf(var + 1e-5f);
        sc[t] = s; sh[t] = b[t] - m * s;
    }
    __syncthreads();
    int idx = blockIdx.x * blockDim.x + t;
    int i = idx >> 4, c = idx & 15;
    if (i >= n) return;
    float4 v = ((const float4*)y)[(size_t)i * 16 + c];
    v.x = lrelu(v.x * sc[c * 4 + 0] + sh[c * 4 + 0]);
    v.y = lrelu(v.y * sc[c * 4 + 1] + sh[c * 4 + 1]);
    v.z = lrelu(v.z * sc[c * 4 + 2] + sh[c * 4 + 2]);
    v.w = lrelu(v.w * sc[c * 4 + 3] + sh[c * 4 + 3]);
    ((float4*)(out + (size_t)i * ldo + off))[c] = v;
}

// ---------------- head: lrelu(bn(y)) @ fc_w2 + b2 -> sigmoid ----------------
__global__ void head_kernel(const float* __restrict__ y,
                            const float* __restrict__ gsum, const float* __restrict__ gsq,
                            const float* __restrict__ g, const float* __restrict__ b,
                            const float* __restrict__ w2, const float* __restrict__ b2,
                            float* __restrict__ out, int n) {
    __shared__ float sc[64], sh[64];
    int t = threadIdx.x;
    if (t < 64) {
        float invn = 1.0f / (float)n;
        float m = gsum[t] * invn;
        float var = gsq[t] * invn - m * m;
        float s = g[t] * rsqrtf(var + 1e-5f);
        sc[t] = s; sh[t] = b[t] - m * s;
    }
    __syncthreads();
    int lane = t & 31;
    int i = (blockIdx.x * blockDim.x + t) >> 5;
    if (i >= n) return;
    float2 v = ((const float2*)y)[(size_t)i * 32 + lane];
    float z0 = lrelu(v.x * sc[2 * lane] + sh[2 * lane]);
    float z1 = lrelu(v.y * sc[2 * lane + 1] + sh[2 * lane + 1]);
    float a = z0 * w2[2 * lane] + z1 * w2[2 * lane + 1];
    #pragma unroll
    for (int o = 16; o; o >>= 1) a += __shfl_xor_sync(0xffffffffu, a, o);
    if (lane == 0) out[i] = 1.0f / (1.0f + expf(-(a + b2[0])));
}

// ---------------- launch ----------------
extern "C" void kernel_launch(void* const* d_in, const int* in_sizes, int n_in,
                              void* d_out, int out_size) {
    const int*   node_deg = (const int*)d_in[0];
    const int*   node_lab = (const int*)d_in[1];
    const int*   edge     = (const int*)d_in[2];
    const float* emb_deg  = (const float*)d_in[3];
    const float* emb_lab  = (const float*)d_in[4];
    const float* l0_w1 = (const float*)d_in[5];
    const float* l0_b1 = (const float*)d_in[6];
    const float* l0_w2 = (const float*)d_in[7];
    const float* l0_b2 = (const float*)d_in[8];
    const float* l0_eps = (const float*)d_in[9];
    const float* bn0_g = (const float*)d_in[10];
    const float* bn0_b = (const float*)d_in[11];
    const float* l1_w1 = (const float*)d_in[12];
    const float* l1_b1 = (const float*)d_in[13];
    const float* l1_w2 = (const float*)d_in[14];
    const float* l1_b2 = (const float*)d_in[15];
    const float* l1_eps = (const float*)d_in[16];
    const float* bn1_g = (const float*)d_in[17];
    const float* bn1_b = (const float*)d_in[18];
    const float* fc_w1 = (const float*)d_in[19];
    const float* fc_b1 = (const float*)d_in[20];
    const float* fc_bn_g = (const float*)d_in[21];
    const float* fc_bn_b = (const float*)d_in[22];
    const float* fc_w2 = (const float*)d_in[23];
    const float* fc_b2 = (const float*)d_in[24];

    int n = in_sizes[0];
    int E = in_sizes[2] / 2;

    float *t0, *XC, *agg, *tbuf, *ybuf, *hb, *sumv, *sqv;
    cudaGetSymbolAddress((void**)&t0,   d_t0);
    cudaGetSymbolAddress((void**)&XC,   d_XC);
    cudaGetSymbolAddress((void**)&agg,  d_agg);
    cudaGetSymbolAddress((void**)&tbuf, d_tbuf);
    cudaGetSymbolAddress((void**)&ybuf, d_ybuf);
    cudaGetSymbolAddress((void**)&hb,   d_hb);
    cudaGetSymbolAddress((void**)&sumv, d_sum);
    cudaGetSymbolAddress((void**)&sqv,  d_sq);

    int NB = (n + 1023) / 1024;

    // init + dictionary tables + per-node lookups + CSR build
    zero_kernel<<<(n + 255) / 256, 256>>>(n);
    tables_kernel<<<162, 128>>>(emb_deg, emb_lab, l0_w1, fc_w1);
    t0hb_kernel<<<(n * 48 + 255) / 256, 256>>>(node_deg, node_lab, fc_b1, n);
    count_kernel<<<(E + 255) / 256, 256>>>(edge, E);
    scanA_kernel<<<NB, 1024>>>(n);
    scanB_kernel<<<1, 32>>>(NB, n);
    scanC_kernel<<<NB, 1024>>>(n);
    fill_kernel<<<(E + 255) / 256, 256>>>(edge, E);

    // ---- GIN layer 0 (folded): z1 = lrelu((1+eps)t0 + A t0 + b1); y = z1 @ w2 + b2 ----
    gather_kernel<128, true><<<((size_t)n * 32 + 255) / 256, 256>>>(t0, 128, agg, 128, l0_eps, l0_b1, n);
    gemm64_kernel<128, false, true, false><<<(n + 127) / 128, 256>>>(agg, 128, l0_w2, l0_b2, nullptr, ybuf, sumv + 0, sqv + 0, n);
    bnapply_kernel<<<((size_t)n * 16 + 255) / 256, 256>>>(ybuf, sumv + 0, sqv + 0, bn0_g, bn0_b, XC, 128, 0, n);

    // ---- GIN layer 1 ----
    gather_kernel<64, false><<<(((size_t)(n + 1) / 2) * 32 + 255) / 256, 256>>>(XC, 128, agg, 64, l1_eps, nullptr, n);
    gemm64_kernel<64, true, false, false><<<(n + 127) / 128, 256>>>(agg, 64, l1_w1, l1_b1, nullptr, tbuf, nullptr, nullptr, n);
    gemm64_kernel<64, false, true, false><<<(n + 127) / 128, 256>>>(tbuf, 64, l1_w2, l1_b2, nullptr, ybuf, sumv + 64, sqv + 64, n);
    bnapply_kernel<<<((size_t)n * 16 + 255) / 256, 256>>>(ybuf, sumv + 64, sqv + 64, bn1_g, bn1_b, XC, 128, 64, n);

    // ---- head (h0 part folded into hb): y = [h1|h2] @ fc_w1[128:256] + hb ----
    gemm64_kernel<128, false, true, true><<<(n + 127) / 128, 256>>>(XC, 128, fc_w1 + 128 * 64, nullptr, hb, ybuf, sumv + 128, sqv + 128, n);
    head_kernel<<<((size_t)n * 32 + 255) / 256, 256>>>(ybuf, sumv + 128, sqv + 128, fc_bn_g, fc_bn_b, fc_w2, fc_b2, (float*)d_out, n);
}

// round 3
// speedup vs baseline: 2.1040x; 1.3552x over previous
#include <cuda_runtime.h>
#include <cuda_bf16.h>
#include <math.h>

// ---------------- problem constants ----------------
#define NMAX 100000
#define EMAX 1200000

// ---------------- device scratch ----------------
__device__ float d_XC[(size_t)NMAX * 128];   // [h1(64) | h2(64)]
__device__ float d_agg[(size_t)NMAX * 128];  // gather output
__device__ float d_ybuf[(size_t)NMAX * 64];  // pre-BN output
__device__ float d_hb[(size_t)NMAX * 64];    // head per-node row bias
__device__ float d_Tdeg[65 * 128];
__device__ float d_Tlab[16 * 128];
__device__ float d_Fdeg[65 * 64];
__device__ float d_Flab[16 * 64];
__device__ int   d_code[NMAX];
__device__ int   d_cnt[NMAX];
__device__ int   d_cursor[NMAX];
__device__ int   d_rowstart[NMAX + 1];
__device__ int   d_col[EMAX];
__device__ int   d_bsum[256];
__device__ int   d_boff[256];
__device__ float d_sum[3 * 64];
__device__ float d_sq[3 * 64];

__device__ __forceinline__ float lrelu(float x) { return x > 0.f ? x : 0.01f * x; }

// ---------------- init: zero counters + stats; pack codes ----------------
__global__ void zero_kernel(const int* __restrict__ deg, const int* __restrict__ lab, int n) {
    int i = blockIdx.x * blockDim.x + threadIdx.x;
    if (i < n) {
        d_cnt[i] = 0; d_cursor[i] = 0;
        d_code[i] = (deg[i] << 4) | lab[i];
    }
    if (i < 192) { d_sum[i] = 0.f; d_sq[i] = 0.f; }
}

// ---------------- dictionary tables: emb @ weight-slices ----------------
__global__ void tables_kernel(const float* __restrict__ emb_deg,
                              const float* __restrict__ emb_lab,
                              const float* __restrict__ l0_w1,
                              const float* __restrict__ fc_w1) {
    __shared__ float e[64];
    int b = blockIdx.x, t = threadIdx.x;
    const float* erow; const float* w; float* out; int H;
    if (b < 65)       { erow = emb_deg + b * 64;         w = l0_w1;            out = d_Tdeg + b * 128;         H = 128; }
    else if (b < 81)  { erow = emb_lab + (b - 65) * 64;  w = l0_w1 + 64 * 128; out = d_Tlab + (b - 65) * 128;  H = 128; }
    else if (b < 146) { erow = emb_deg + (b - 81) * 64;  w = fc_w1;            out = d_Fdeg + (b - 81) * 64;   H = 64;  }
    else              { erow = emb_lab + (b - 146) * 64; w = fc_w1 + 64 * 64;  out = d_Flab + (b - 146) * 64;  H = 64;  }
    if (t < 64) e[t] = erow[t];
    __syncthreads();
    if (t < H) {
        float s = 0.f;
        #pragma unroll 8
        for (int k = 0; k < 64; k++) s += e[k] * w[k * H + t];
        out[t] = s;
    }
}

// ---------------- per-node head row-bias: hb = Fdeg[deg]+Flab[lab]+fc_b1 ----------------
__global__ void hb_kernel(const float* __restrict__ fc_b1, int n) {
    int idx = blockIdx.x * blockDim.x + threadIdx.x;
    int i = idx >> 4, c = idx & 15;
    if (i >= n) return;
    int code = d_code[i];
    float4 a = ((const float4*)d_Fdeg)[(code >> 4) * 16 + c];
    float4 b = ((const float4*)d_Flab)[(code & 15) * 16 + c];
    float4 bb = ((const float4*)fc_b1)[c];
    ((float4*)d_hb)[(size_t)i * 16 + c] =
        make_float4(a.x + b.x + bb.x, a.y + b.y + bb.y, a.z + b.z + bb.z, a.w + b.w + bb.w);
}

// ---------------- CSR build ----------------
__global__ void count_kernel(const int* __restrict__ edge, int e) {
    int i = blockIdx.x * blockDim.x + threadIdx.x;
    if (i < e) atomicAdd(&d_cnt[edge[e + i]], 1);
}

__global__ void scanA_kernel(int n) {
    __shared__ int wsum[32];
    int t = threadIdx.x;
    int idx = blockIdx.x * 1024 + t;
    int v = (idx < n) ? d_cnt[idx] : 0;
    #pragma unroll
    for (int o = 16; o; o >>= 1) v += __shfl_xor_sync(0xffffffffu, v, o);
    if ((t & 31) == 0) wsum[t >> 5] = v;
    __syncthreads();
    if (t < 32) {
        int s = wsum[t];
        #pragma unroll
        for (int o = 16; o; o >>= 1) s += __shfl_xor_sync(0xffffffffu, s, o);
        if (t == 0) d_bsum[blockIdx.x] = s;
    }
}

__global__ void scanB_kernel(int nb, int n) {
    if (threadIdx.x == 0 && blockIdx.x == 0) {
        int run = 0;
        for (int b = 0; b < nb; b++) { d_boff[b] = run; run += d_bsum[b]; }
        d_rowstart[n] = run;
    }
}

__global__ void scanC_kernel(int n) {
    __shared__ int wsum[32];
    int t = threadIdx.x;
    int idx = blockIdx.x * 1024 + t;
    int v = (idx < n) ? d_cnt[idx] : 0;
    int lane = t & 31, wid = t >> 5;
    int inc = v;
    #pragma unroll
    for (int o = 1; o < 32; o <<= 1) {
        int u = __shfl_up_sync(0xffffffffu, inc, o);
        if (lane >= o) inc += u;
    }
    if (lane == 31) wsum[wid] = inc;
    __syncthreads();
    if (t < 32) {
        int s = wsum[t];
        int sInc = s;
        #pragma unroll
        for (int o = 1; o < 32; o <<= 1) {
            int u = __shfl_up_sync(0xffffffffu, sInc, o);
            if (t >= o) sInc += u;
        }
        wsum[t] = sInc - s;
    }
    __syncthreads();
    if (idx < n) d_rowstart[idx] = d_boff[blockIdx.x] + wsum[wid] + inc - v;
}

__global__ void fill_kernel(const int* __restrict__ edge, int e) {
    int i = blockIdx.x * blockDim.x + threadIdx.x;
    if (i < e) {
        int d = edge[e + i];
        int p = atomicAdd(&d_cursor[d], 1);
        d_col[d_rowstart[d] + p] = edge[i];
    }
}

// ---------------- layer-0 aggregation from smem dictionary tables ----------------
// z1[i] = lrelu( (1+eps)*(Tdeg[dg_i]+Tlab[lb_i]) + sum_nbr (Tdeg[dg_j]+Tlab[lb_j]) + b1 )
__global__ void __launch_bounds__(256)
gather0_kernel(const float* __restrict__ epsp, const float* __restrict__ b1, int n) {
    __shared__ __align__(16) float sTd[65 * 128];
    __shared__ __align__(16) float sTl[16 * 128];
    int t = threadIdx.x;
    {
        const float4* src = (const float4*)d_Tdeg;
        float4* dst = (float4*)sTd;
        for (int j = t; j < 65 * 32; j += 256) dst[j] = src[j];
        const float4* src2 = (const float4*)d_Tlab;
        float4* dst2 = (float4*)sTl;
        for (int j = t; j < 16 * 32; j += 256) dst2[j] = src2[j];
    }
    __syncthreads();
    const float4* Td4 = (const float4*)sTd;
    const float4* Tl4 = (const float4*)sTl;
    int lane = t & 31, w = t >> 5;
    int c = lane;
    float e1 = 1.0f + epsp[0];
    float4 b4 = ((const float4*)b1)[c];
    int base_node = blockIdx.x * 256 + w * 32;
    for (int it = 0; it < 32; it++) {
        int i = base_node + it;
        if (i >= n) break;
        int js = d_rowstart[i], je = d_rowstart[i + 1];
        int self = d_code[i];
        float4 a = Td4[(self >> 4) * 32 + c];
        float4 bsl = Tl4[(self & 15) * 32 + c];
        float4 s = make_float4(e1 * (a.x + bsl.x), e1 * (a.y + bsl.y),
                               e1 * (a.z + bsl.z), e1 * (a.w + bsl.w));
        for (int bs = js; bs < je; bs += 32) {
            int idx = bs + lane;
            int code = (idx < je) ? d_code[d_col[idx]] : 0;
            int m = min(32, je - bs);
            for (int j = 0; j < m; j++) {
                int cd = __shfl_sync(0xffffffffu, code, j);
                float4 u = Td4[(cd >> 4) * 32 + c];
                float4 v = Tl4[(cd & 15) * 32 + c];
                s.x += u.x + v.x; s.y += u.y + v.y;
                s.z += u.z + v.z; s.w += u.w + v.w;
            }
        }
        s.x = lrelu(s.x + b4.x); s.y = lrelu(s.y + b4.y);
        s.z = lrelu(s.z + b4.z); s.w = lrelu(s.w + b4.w);
        ((float4*)d_agg)[(size_t)i * 32 + c] = s;
    }
}

// ---------------- layer-1 aggregation (64-wide gather from XC) ----------------
__global__ void gather1_kernel(const float* __restrict__ hsrc, int ldh,
                               const float* __restrict__ epsp, int n) {
    int lane = threadIdx.x & 31;
    int warp = (blockIdx.x * blockDim.x + threadIdx.x) >> 5;
    int i = warp * 2 + (lane >> 4);
    int c = lane & 15;
    if (i >= n) return;
    float e1 = 1.0f + epsp[0];
    const float4* hb4 = (const float4*)hsrc;
    int ldh4 = ldh >> 2;
    float4 a = hb4[(size_t)i * ldh4 + c];
    float4 s = make_float4(a.x * e1, a.y * e1, a.z * e1, a.w * e1);
    int js = d_rowstart[i], je = d_rowstart[i + 1];
    for (int j = js; j < je; j++) {
        int nb = d_col[j];
        float4 v = hb4[(size_t)nb * ldh4 + c];
        s.x += v.x; s.y += v.y; s.z += v.z; s.w += v.w;
    }
    ((float4*)d_agg)[(size_t)i * 16 + c] = s;
}

// ---------------- stats epilogue helper (per-thread 8 cols over 4 nodes) ----------------
__device__ __forceinline__ void stats_reduce(float (&ps)[8], float (&pq)[8],
                                             float* csum, float* csq, int og, int lane) {
    #pragma unroll
    for (int o = 8; o <= 16; o <<= 1) {
        #pragma unroll
        for (int j = 0; j < 8; j++) {
            ps[j] += __shfl_xor_sync(0xffffffffu, ps[j], o);
            pq[j] += __shfl_xor_sync(0xffffffffu, pq[j], o);
        }
    }
    if (lane < 8) {
        #pragma unroll
        for (int j = 0; j < 8; j++) {
            atomicAdd(&csum[og * 8 + j], ps[j]);
            atomicAdd(&csq[og * 8 + j], pq[j]);
        }
    }
}

// ---------------- register-tiled fp32 GEMM: y[n,64] = x[n,K] @ w[K,64] + bias(/rowbias) ----------------
template <int K, bool STATS, bool RB>
__global__ void __launch_bounds__(256, 2)
gemm64_kernel(const float* __restrict__ x, int ldx,
              const float* __restrict__ w,
              const float* __restrict__ bias,
              const float* __restrict__ rowbias,
              float* __restrict__ y,
              float* __restrict__ gsum, float* __restrict__ gsq, int n) {
    constexpr int KC = 32;
    __shared__ float xs[128][33];
    __shared__ __align__(16) float ws[KC][64];
    __shared__ float csum[64], csq[64];

    const int t = threadIdx.x;
    const int og = t & 7;
    const int ng = t >> 3;
    const int lane = t & 31;
    const int node0 = blockIdx.x * 128;

    if (STATS) {
        if (t < 64) { csum[t] = 0.f; csq[t] = 0.f; }
    }

    float acc[4][8];
    #pragma unroll
    for (int i = 0; i < 4; i++)
        #pragma unroll
        for (int j = 0; j < 8; j++) acc[i][j] = 0.f;

    for (int k0 = 0; k0 < K; k0 += KC) {
        {
            int row = t >> 1;
            int cb = (t & 1) * 16;
            int gn = node0 + row;
            const float4* src = (const float4*)(x + (size_t)gn * ldx + k0 + cb);
            #pragma unroll
            for (int i = 0; i < 4; i++) {
                float4 v = (gn < n) ? src[i] : make_float4(0.f, 0.f, 0.f, 0.f);
                xs[row][cb + 4 * i + 0] = v.x;
                xs[row][cb + 4 * i + 1] = v.y;
                xs[row][cb + 4 * i + 2] = v.z;
                xs[row][cb + 4 * i + 3] = v.w;
            }
        }
        {
            const float4* wsrc = (const float4*)(w + (size_t)k0 * 64);
            float4* wdst = (float4*)(&ws[0][0]);
            wdst[t] = wsrc[t];
            wdst[t + 256] = wsrc[t + 256];
        }
        __syncthreads();
        #pragma unroll
        for (int k = 0; k < KC; k++) {
            float4 w0 = *(const float4*)(&ws[k][og * 8]);
            float4 w1v = *(const float4*)(&ws[k][og * 8 + 4]);
            float xv[4];
            #pragma unroll
            for (int i = 0; i < 4; i++) xv[i] = xs[ng * 4 + i][k];
            #pragma unroll
            for (int i = 0; i < 4; i++) {
                acc[i][0] += xv[i] * w0.x;  acc[i][1] += xv[i] * w0.y;
                acc[i][2] += xv[i] * w0.z;  acc[i][3] += xv[i] * w0.w;
                acc[i][4] += xv[i] * w1v.x; acc[i][5] += xv[i] * w1v.y;
                acc[i][6] += xv[i] * w1v.z; acc[i][7] += xv[i] * w1v.w;
            }
        }
        __syncthreads();
    }

    float b8[8];
    if (!RB) {
        #pragma unroll
        for (int j = 0; j < 8; j++) b8[j] = bias[og * 8 + j];
    }

    float ps[8], pq[8];
    #pragma unroll
    for (int j = 0; j < 8; j++) { ps[j] = 0.f; pq[j] = 0.f; }

    #pragma unroll
    for (int i = 0; i < 4; i++) {
        int gn = node0 + ng * 4 + i;
        if (gn < n) {
            float r[8];
            if (RB) {
                float4 r0 = ((const float4*)(rowbias + (size_t)gn * 64 + og * 8))[0];
                float4 r1 = ((const float4*)(rowbias + (size_t)gn * 64 + og * 8))[1];
                r[0] = r0.x; r[1] = r0.y; r[2] = r0.z; r[3] = r0.w;
                r[4] = r1.x; r[5] = r1.y; r[6] = r1.z; r[7] = r1.w;
            }
            float v[8];
            #pragma unroll
            for (int j = 0; j < 8; j++) {
                float z = acc[i][j] + (RB ? r[j] : b8[j]);
                v[j] = z;
                if (STATS) { ps[j] += z; pq[j] += z * z; }
            }
            float4* yr = (float4*)(y + (size_t)gn * 64 + og * 8);
            yr[0] = make_float4(v[0], v[1], v[2], v[3]);
            yr[1] = make_float4(v[4], v[5], v[6], v[7]);
        }
    }
    if (STATS) {
        stats_reduce(ps, pq, csum, csq, og, lane);
        __syncthreads();
        if (t < 64) {
            atomicAdd(&gsum[t], csum[t]);
            atomicAdd(&gsq[t], csq[t]);
        }
    }
}

// ---------------- fused layer-1 MLP: y = lrelu(x@w1+b1) @ w2 + b2, with stats ----------------
__global__ void __launch_bounds__(256, 2)
mlp1_kernel(const float* __restrict__ x,
            const float* __restrict__ w1, const float* __restrict__ b1,
            const float* __restrict__ w2, const float* __restrict__ b2,
            float* __restrict__ y,
            float* __restrict__ gsum, float* __restrict__ gsq, int n) {
    constexpr int KC = 32;
    __shared__ float xs[128][33];
    __shared__ __align__(16) float ws[KC][64];
    __shared__ float hs[128][65];
    __shared__ float csum[64], csq[64];

    const int t = threadIdx.x;
    const int og = t & 7;
    const int ng = t >> 3;
    const int lane = t & 31;
    const int node0 = blockIdx.x * 128;

    if (t < 64) { csum[t] = 0.f; csq[t] = 0.f; }

    float acc[4][8];
    #pragma unroll
    for (int i = 0; i < 4; i++)
        #pragma unroll
        for (int j = 0; j < 8; j++) acc[i][j] = 0.f;

    // stage 1: hidden = lrelu(x @ w1 + b1) -> hs
    for (int k0 = 0; k0 < 64; k0 += KC) {
        {
            int row = t >> 1;
            int cb = (t & 1) * 16;
            int gn = node0 + row;
            const float4* src = (const float4*)(x + (size_t)gn * 64 + k0 + cb);
            #pragma unroll
            for (int i = 0; i < 4; i++) {
                float4 v = (gn < n) ? src[i] : make_float4(0.f, 0.f, 0.f, 0.f);
                xs[row][cb + 4 * i + 0] = v.x;
                xs[row][cb + 4 * i + 1] = v.y;
                xs[row][cb + 4 * i + 2] = v.z;
                xs[row][cb + 4 * i + 3] = v.w;
            }
        }
        {
            const float4* wsrc = (const float4*)(w1 + (size_t)k0 * 64);
            float4* wdst = (float4*)(&ws[0][0]);
            wdst[t] = wsrc[t];
            wdst[t + 256] = wsrc[t + 256];
        }
        __syncthreads();
        #pragma unroll
        for (int k = 0; k < KC; k++) {
            float4 w0 = *(const float4*)(&ws[k][og * 8]);
            float4 w1v = *(const float4*)(&ws[k][og * 8 + 4]);
            float xv[4];
            #pragma unroll
            for (int i = 0; i < 4; i++) xv[i] = xs[ng * 4 + i][k];
            #pragma unroll
            for (int i = 0; i < 4; i++) {
                acc[i][0] += xv[i] * w0.x;  acc[i][1] += xv[i] * w0.y;
                acc[i][2] += xv[i] * w0.z;  acc[i][3] += xv[i] * w0.w;
                acc[i][4] += xv[i] * w1v.x; acc[i][5] += xv[i] * w1v.y;
                acc[i][6] += xv[i] * w1v.z; acc[i][7] += xv[i] * w1v.w;
            }
        }
        __syncthreads();
    }
    {
        float b8[8];
        #pragma unroll
        for (int j = 0; j < 8; j++) b8[j] = b1[og * 8 + j];
        #pragma unroll
        for (int i = 0; i < 4; i++) {
            #pragma unroll
            for (int j = 0; j < 8; j++)
                hs[ng * 4 + i][og * 8 + j] = lrelu(acc[i][j] + b8[j]);
        }
    }
    // reset accumulators
    #pragma unroll
    for (int i = 0; i < 4; i++)
        #pragma unroll
        for (int j = 0; j < 8; j++) acc[i][j] = 0.f;
    __syncthreads();

    // stage 2: y = hidden @ w2 + b2
    for (int k0 = 0; k0 < 64; k0 += KC) {
        {
            const float4* wsrc = (const float4*)(w2 + (size_t)k0 * 64);
            float4* wdst = (float4*)(&ws[0][0]);
            wdst[t] = wsrc[t];
            wdst[t + 256] = wsrc[t + 256];
        }
        __syncthreads();
        #pragma unroll
        for (int k = 0; k < KC; k++) {
            float4 w0 = *(const float4*)(&ws[k][og * 8]);
            float4 w1v = *(const float4*)(&ws[k][og * 8 + 4]);
            float xv[4];
            #pragma unroll
            for (int i = 0; i < 4; i++) xv[i] = hs[ng * 4 + i][k0 + k];
            #pragma unroll
            for (int i = 0; i < 4; i++) {
                acc[i][0] += xv[i] * w0.x;  acc[i][1] += xv[i] * w0.y;
                acc[i][2] += xv[i] * w0.z;  acc[i][3] += xv[i] * w0.w;
                acc[i][4] += xv[i] * w1v.x; acc[i][5] += xv[i] * w1v.y;
                acc[i][6] += xv[i] * w1v.z; acc[i][7] += xv[i] * w1v.w;
            }
        }
        __syncthreads();
    }

    float b8[8];
    #pragma unroll
    for (int j = 0; j < 8; j++) b8[j] = b2[og * 8 + j];

    float ps[8], pq[8];
    #pragma unroll
    for (int j = 0; j < 8; j++) { ps[j] = 0.f; pq[j] = 0.f; }

    #pragma unroll
    for (int i = 0; i < 4; i++) {
        int gn = node0 + ng * 4 + i;
        if (gn < n) {
            float v[8];
            #pragma unroll
            for (int j = 0; j < 8; j++) {
                float z = acc[i][j] + b8[j];
                v[j] = z;
                ps[j] += z; pq[j] += z * z;
            }
            float4* yr = (float4*)(y + (size_t)gn * 64 + og * 8);
            yr[0] = make_float4(v[0], v[1], v[2], v[3]);
            yr[1] = make_float4(v[4], v[5], v[6], v[7]);
        }
    }
    stats_reduce(ps, pq, csum, csq, og, lane);
    __syncthreads();
    if (t < 64) {
        atomicAdd(&gsum[t], csum[t]);
        atomicAdd(&gsq[t], csq[t]);
    }
}

// ---------------- BN apply + lrelu ----------------
__global__ void bnapply_kernel(const float* __restrict__ y,
                               const float* __restrict__ gsum, const float* __restrict__ gsq,
                               const float* __restrict__ g, const float* __restrict__ b,
                               float* __restrict__ out, int ldo, int off, int n) {
    __shared__ float sc[64], sh[64];
    int t = threadIdx.x;
    if (t < 64) {
        float invn = 1.0f / (float)n;
        float m = gsum[t] * invn;
        float var = gsq[t] * invn - m * m;
        float s = g[t] * rsqrtf(var + 1e-5f);
        sc[t] = s; sh[t] = b[t] - m * s;
    }
    __syncthreads();
    int idx = blockIdx.x * blockDim.x + t;
    int i = idx >> 4, c = idx & 15;
    if (i >= n) return;
    float4 v = ((const float4*)y)[(size_t)i * 16 + c];
    v.x = lrelu(v.x * sc[c * 4 + 0] + sh[c * 4 + 0]);
    v.y = lrelu(v.y * sc[c * 4 + 1] + sh[c * 4 + 1]);
    v.z = lrelu(v.z * sc[c * 4 + 2] + sh[c * 4 + 2]);
    v.w = lrelu(v.w * sc[c * 4 + 3] + sh[c * 4 + 3]);
    ((float4*)(out + (size_t)i * ldo + off))[c] = v;
}

// ---------------- head: lrelu(bn(y)) @ fc_w2 + b2 -> sigmoid ----------------
__global__ void head_kernel(const float* __restrict__ y,
                            const float* __restrict__ gsum, const float* __restrict__ gsq,
                            const float* __restrict__ g, const float* __restrict__ b,
                            const float* __restrict__ w2, const float* __restrict__ b2,
                            float* __restrict__ out, int n) {
    __shared__ float sc[64], sh[64];
    int t = threadIdx.x;
    if (t < 64) {
        float invn = 1.0f / (float)n;
        float m = gsum[t] * invn;
        float var = gsq[t] * invn - m * m;
        float s = g[t] * rsqrtf(var + 1e-5f);
        sc[t] = s; sh[t] = b[t] - m * s;
    }
    __syncthreads();
    int lane = t & 31;
    int i = (blockIdx.x * blockDim.x + t) >> 5;
    if (i >= n) return;
    float2 v = ((const float2*)y)[(size_t)i * 32 + lane];
    float z0 = lrelu(v.x * sc[2 * lane] + sh[2 * lane]);
    float z1 = lrelu(v.y * sc[2 * lane + 1] + sh[2 * lane + 1]);
    float a = z0 * w2[2 * lane] + z1 * w2[2 * lane + 1];
    #pragma unroll
    for (int o = 16; o; o >>= 1) a += __shfl_xor_sync(0xffffffffu, a, o);
    if (lane == 0) out[i] = 1.0f / (1.0f + expf(-(a + b2[0])));
}

// ---------------- launch ----------------
extern "C" void kernel_launch(void* const* d_in, const int* in_sizes, int n_in,
                              void* d_out, int out_size) {
    const int*   node_deg = (const int*)d_in[0];
    const int*   node_lab = (const int*)d_in[1];
    const int*   edge     = (const int*)d_in[2];
    const float* emb_deg  = (const float*)d_in[3];
    const float* emb_lab  = (const float*)d_in[4];
    const float* l0_w1 = (const float*)d_in[5];
    const float* l0_b1 = (const float*)d_in[6];
    const float* l0_w2 = (const float*)d_in[7];
    const float* l0_b2 = (const float*)d_in[8];
    const float* l0_eps = (const float*)d_in[9];
    const float* bn0_g = (const float*)d_in[10];
    const float* bn0_b = (const float*)d_in[11];
    const float* l1_w1 = (const float*)d_in[12];
    const float* l1_b1 = (const float*)d_in[13];
    const float* l1_w2 = (const float*)d_in[14];
    const float* l1_b2 = (const float*)d_in[15];
    const float* l1_eps = (const float*)d_in[16];
    const float* bn1_g = (const float*)d_in[17];
    const float* bn1_b = (const float*)d_in[18];
    const float* fc_w1 = (const float*)d_in[19];
    const float* fc_b1 = (const float*)d_in[20];
    const float* fc_bn_g = (const float*)d_in[21];
    const float* fc_bn_b = (const float*)d_in[22];
    const float* fc_w2 = (const float*)d_in[23];
    const float* fc_b2 = (const float*)d_in[24];

    int n = in_sizes[0];
    int E = in_sizes[2] / 2;

    float *XC, *agg, *ybuf, *hb, *sumv, *sqv;
    cudaGetSymbolAddress((void**)&XC,   d_XC);
    cudaGetSymbolAddress((void**)&agg,  d_agg);
    cudaGetSymbolAddress((void**)&ybuf, d_ybuf);
    cudaGetSymbolAddress((void**)&hb,   d_hb);
    cudaGetSymbolAddress((void**)&sumv, d_sum);
    cudaGetSymbolAddress((void**)&sqv,  d_sq);

    int NB = (n + 1023) / 1024;

    // init + tables + head rowbias + CSR build
    zero_kernel<<<(n + 255) / 256, 256>>>(node_deg, node_lab, n);
    tables_kernel<<<162, 128>>>(emb_deg, emb_lab, l0_w1, fc_w1);
    hb_kernel<<<((size_t)n * 16 + 255) / 256, 256>>>(fc_b1, n);
    count_kernel<<<(E + 255) / 256, 256>>>(edge, E);
    scanA_kernel<<<NB, 1024>>>(n);
    scanB_kernel<<<1, 32>>>(NB, n);
    scanC_kernel<<<NB, 1024>>>(n);
    fill_kernel<<<(E + 255) / 256, 256>>>(edge, E);

    // ---- GIN layer 0 (dictionary gather): z1 -> agg; y = z1 @ w2 + b2 ----
    gather0_kernel<<<(n + 255) / 256, 256>>>(l0_eps, l0_b1, n);
    gemm64_kernel<128, true, false><<<(n + 127) / 128, 256>>>(agg, 128, l0_w2, l0_b2, nullptr, ybuf, sumv + 0, sqv + 0, n);
    bnapply_kernel<<<((size_t)n * 16 + 255) / 256, 256>>>(ybuf, sumv + 0, sqv + 0, bn0_g, bn0_b, XC, 128, 0, n);

    // ---- GIN layer 1: gather + fused MLP ----
    gather1_kernel<<<((size_t)((n + 1) / 2) * 32 + 255) / 256, 256>>>(XC, 128, l1_eps, n);
    mlp1_kernel<<<(n + 127) / 128, 256>>>(agg, l1_w1, l1_b1, l1_w2, l1_b2, ybuf, sumv + 64, sqv + 64, n);
    bnapply_kernel<<<((size_t)n * 16 + 255) / 256, 256>>>(ybuf, sumv + 64, sqv + 64, bn1_g, bn1_b, XC, 128, 64, n);

    // ---- head ----
    gemm64_kernel<128, true, true><<<(n + 127) / 128, 256>>>(XC, 128, fc_w1 + 128 * 64, nullptr, hb, ybuf, sumv + 128, sqv + 128, n);
    head_kernel<<<((size_t)n * 32 + 255) / 256, 256>>>(ybuf, sumv + 128, sqv + 128, fc_bn_g, fc_bn_b, fc_w2, fc_b2, (float*)d_out, n);
}

// round 5
// speedup vs baseline: 2.7662x; 1.3147x over previous
#include <cuda_runtime.h>
#include <cuda_bf16.h>
#include <math.h>
#include <stdint.h>

// ---------------- problem constants ----------------
#define NMAX 100000
#define EMAX 1200000

// ---------------- device scratch ----------------
__device__ float d_XC[(size_t)NMAX * 128];   // [h1(64) | h2(64)]
__device__ float d_agg[(size_t)NMAX * 128];  // gather output
__device__ float d_ybuf[(size_t)NMAX * 64];  // pre-BN output
__device__ float d_hb[(size_t)NMAX * 64];    // head per-node row bias
__device__ float d_Tdeg[65 * 128];
__device__ float d_Tlab[16 * 128];
__device__ float d_Fdeg[65 * 64];
__device__ float d_Flab[16 * 64];
__device__ int   d_code[NMAX];
__device__ int   d_cnt[NMAX];
__device__ int   d_cursor[NMAX];
__device__ int   d_rowstart[NMAX + 1];
__device__ int   d_col[EMAX];
__device__ int   d_bsum[256];
__device__ int   d_boff[256];
__device__ float d_sum[3 * 64];
__device__ float d_sq[3 * 64];

__device__ __forceinline__ float lrelu(float x) { return x > 0.f ? x : 0.01f * x; }

__device__ __forceinline__ float to_tf32(float x) {
    float r;
    asm("cvt.rna.tf32.f32 %0, %1;" : "=f"(r) : "f"(x));
    return r;
}

// mma.sync m16n8k8 tf32: D += A(16x8) * B(8x8), fp32 accumulate
__device__ __forceinline__ void mma_tf32(float (&d)[4], const uint32_t (&a)[4], const uint32_t (&b)[2]) {
    asm volatile("mma.sync.aligned.m16n8k8.row.col.f32.tf32.tf32.f32 "
        "{%0,%1,%2,%3}, {%4,%5,%6,%7}, {%8,%9}, {%0,%1,%2,%3};"
        : "+f"(d[0]), "+f"(d[1]), "+f"(d[2]), "+f"(d[3])
        : "r"(a[0]), "r"(a[1]), "r"(a[2]), "r"(a[3]), "r"(b[0]), "r"(b[1]));
}

// ---------------- init: zero counters + stats; pack codes ----------------
__global__ void zero_kernel(const int* __restrict__ deg, const int* __restrict__ lab, int n) {
    int i = blockIdx.x * blockDim.x + threadIdx.x;
    if (i < n) {
        d_cnt[i] = 0; d_cursor[i] = 0;
        d_code[i] = (deg[i] << 4) | lab[i];
    }
    if (i < 192) { d_sum[i] = 0.f; d_sq[i] = 0.f; }
}

// ---------------- dictionary tables: emb @ weight-slices ----------------
__global__ void tables_kernel(const float* __restrict__ emb_deg,
                              const float* __restrict__ emb_lab,
                              const float* __restrict__ l0_w1,
                              const float* __restrict__ fc_w1) {
    __shared__ float e[64];
    int b = blockIdx.x, t = threadIdx.x;
    const float* erow; const float* w; float* out; int H;
    if (b < 65)       { erow = emb_deg + b * 64;         w = l0_w1;            out = d_Tdeg + b * 128;         H = 128; }
    else if (b < 81)  { erow = emb_lab + (b - 65) * 64;  w = l0_w1 + 64 * 128; out = d_Tlab + (b - 65) * 128;  H = 128; }
    else if (b < 146) { erow = emb_deg + (b - 81) * 64;  w = fc_w1;            out = d_Fdeg + (b - 81) * 64;   H = 64;  }
    else              { erow = emb_lab + (b - 146) * 64; w = fc_w1 + 64 * 64;  out = d_Flab + (b - 146) * 64;  H = 64;  }
    if (t < 64) e[t] = erow[t];
    __syncthreads();
    if (t < H) {
        float s = 0.f;
        #pragma unroll 8
        for (int k = 0; k < 64; k++) s += e[k] * w[k * H + t];
        out[t] = s;
    }
}

// ---------------- per-node head row-bias ----------------
__global__ void hb_kernel(const float* __restrict__ fc_b1, int n) {
    int idx = blockIdx.x * blockDim.x + threadIdx.x;
    int i = idx >> 4, c = idx & 15;
    if (i >= n) return;
    int code = d_code[i];
    float4 a = ((const float4*)d_Fdeg)[(code >> 4) * 16 + c];
    float4 b = ((const float4*)d_Flab)[(code & 15) * 16 + c];
    float4 bb = ((const float4*)fc_b1)[c];
    ((float4*)d_hb)[(size_t)i * 16 + c] =
        make_float4(a.x + b.x + bb.x, a.y + b.y + bb.y, a.z + b.z + bb.z, a.w + b.w + bb.w);
}

// ---------------- CSR build ----------------
__global__ void count_kernel(const int* __restrict__ edge, int e) {
    int i = blockIdx.x * blockDim.x + threadIdx.x;
    if (i < e) atomicAdd(&d_cnt[edge[e + i]], 1);
}

__global__ void scanA_kernel(int n) {
    __shared__ int wsum[32];
    int t = threadIdx.x;
    int idx = blockIdx.x * 1024 + t;
    int v = (idx < n) ? d_cnt[idx] : 0;
    #pragma unroll
    for (int o = 16; o; o >>= 1) v += __shfl_xor_sync(0xffffffffu, v, o);
    if ((t & 31) == 0) wsum[t >> 5] = v;
    __syncthreads();
    if (t < 32) {
        int s = wsum[t];
        #pragma unroll
        for (int o = 16; o; o >>= 1) s += __shfl_xor_sync(0xffffffffu, s, o);
        if (t == 0) d_bsum[blockIdx.x] = s;
    }
}

__global__ void scanB_kernel(int nb, int n) {
    if (threadIdx.x == 0 && blockIdx.x == 0) {
        int run = 0;
        for (int b = 0; b < nb; b++) { d_boff[b] = run; run += d_bsum[b]; }
        d_rowstart[n] = run;
    }
}

__global__ void scanC_kernel(int n) {
    __shared__ int wsum[32];
    int t = threadIdx.x;
    int idx = blockIdx.x * 1024 + t;
    int v = (idx < n) ? d_cnt[idx] : 0;
    int lane = t & 31, wid = t >> 5;
    int inc = v;
    #pragma unroll
    for (int o = 1; o < 32; o <<= 1) {
        int u = __shfl_up_sync(0xffffffffu, inc, o);
        if (lane >= o) inc += u;
    }
    if (lane == 31) wsum[wid] = inc;
    __syncthreads();
    if (t < 32) {
        int s = wsum[t];
        int sInc = s;
        #pragma unroll
        for (int o = 1; o < 32; o <<= 1) {
            int u = __shfl_up_sync(0xffffffffu, sInc, o);
            if (t >= o) sInc += u;
        }
        wsum[t] = sInc - s;
    }
    __syncthreads();
    if (idx < n) d_rowstart[idx] = d_boff[blockIdx.x] + wsum[wid] + inc - v;
}

__global__ void fill_kernel(const int* __restrict__ edge, int e) {
    int i = blockIdx.x * blockDim.x + threadIdx.x;
    if (i < e) {
        int d = edge[e + i];
        int p = atomicAdd(&d_cursor[d], 1);
        d_col[d_rowstart[d] + p] = edge[i];
    }
}

// ---------------- layer-0 aggregation from smem dictionary tables ----------------
__global__ void __launch_bounds__(256)
gather0_kernel(const float* __restrict__ epsp, const float* __restrict__ b1, int n) {
    __shared__ __align__(16) float sTd[65 * 128];
    __shared__ __align__(16) float sTl[16 * 128];
    int t = threadIdx.x;
    {
        const float4* src = (const float4*)d_Tdeg;
        float4* dst = (float4*)sTd;
        for (int j = t; j < 65 * 32; j += 256) dst[j] = src[j];
        const float4* src2 = (const float4*)d_Tlab;
        float4* dst2 = (float4*)sTl;
        for (int j = t; j < 16 * 32; j += 256) dst2[j] = src2[j];
    }
    __syncthreads();
    const float4* Td4 = (const float4*)sTd;
    const float4* Tl4 = (const float4*)sTl;
    int lane = t & 31, w = t >> 5;
    int c = lane;
    float e1 = 1.0f + epsp[0];
    float4 b4 = ((const float4*)b1)[c];
    int base_node = blockIdx.x * 256 + w * 32;
    for (int it = 0; it < 32; it++) {
        int i = base_node + it;
        if (i >= n) break;
        int js = d_rowstart[i], je = d_rowstart[i + 1];
        int self = d_code[i];
        float4 a = Td4[(self >> 4) * 32 + c];
        float4 bsl = Tl4[(self & 15) * 32 + c];
        float4 s = make_float4(e1 * (a.x + bsl.x), e1 * (a.y + bsl.y),
                               e1 * (a.z + bsl.z), e1 * (a.w + bsl.w));
        for (int bs = js; bs < je; bs += 32) {
            int idx = bs + lane;
            int code = (idx < je) ? d_code[d_col[idx]] : 0;
            int m = min(32, je - bs);
            for (int j = 0; j < m; j++) {
                int cd = __shfl_sync(0xffffffffu, code, j);
                float4 u = Td4[(cd >> 4) * 32 + c];
                float4 v = Tl4[(cd & 15) * 32 + c];
                s.x += u.x + v.x; s.y += u.y + v.y;
                s.z += u.z + v.z; s.w += u.w + v.w;
            }
        }
        s.x = lrelu(s.x + b4.x); s.y = lrelu(s.y + b4.y);
        s.z = lrelu(s.z + b4.z); s.w = lrelu(s.w + b4.w);
        ((float4*)d_agg)[(size_t)i * 32 + c] = s;
    }
}

// ---------------- layer-1 aggregation (64-wide gather from XC) ----------------
__global__ void gather1_kernel(const float* __restrict__ hsrc, int ldh,
                               const float* __restrict__ epsp, int n) {
    int lane = threadIdx.x & 31;
    int warp = (blockIdx.x * blockDim.x + threadIdx.x) >> 5;
    int i = warp * 2 + (lane >> 4);
    int c = lane & 15;
    if (i >= n) return;
    float e1 = 1.0f + epsp[0];
    const float4* hb4 = (const float4*)hsrc;
    int ldh4 = ldh >> 2;
    float4 a = hb4[(size_t)i * ldh4 + c];
    float4 s = make_float4(a.x * e1, a.y * e1, a.z * e1, a.w * e1);
    int js = d_rowstart[i], je = d_rowstart[i + 1];
    for (int j = js; j < je; j++) {
        int nb = d_col[j];
        float4 v = hb4[(size_t)nb * ldh4 + c];
        s.x += v.x; s.y += v.y; s.z += v.z; s.w += v.w;
    }
    ((float4*)d_agg)[(size_t)i * 16 + c] = s;
}

// ================= warp-level tf32 MMA GEMM building blocks =================
// A tile in smem: xs[128][KP] padded rows (KP = K+4) — bank-conflict-free frags.
// B tile in smem: wsT[64][KP] (W transposed: wsT[n][k] = w[k*64+n]).

template <int K>
__device__ __forceinline__ void loadA_mma(float* xs, const float* __restrict__ x,
                                          int node0, int n, int t) {
    constexpr int KP = K + 4;
    int r = t >> 1;
    int cb = (t & 1) * (K / 2);
    int gn = node0 + r;
    const float4* src = (const float4*)(x + (size_t)gn * K + cb);
    #pragma unroll
    for (int i = 0; i < K / 8; i++) {
        float4 v = (gn < n) ? src[i] : make_float4(0.f, 0.f, 0.f, 0.f);
        float* dst = xs + r * KP + cb + i * 4;
        dst[0] = to_tf32(v.x); dst[1] = to_tf32(v.y);
        dst[2] = to_tf32(v.z); dst[3] = to_tf32(v.w);
    }
}

template <int K>
__device__ __forceinline__ void loadB_mma(float* wsT, const float* __restrict__ w, int t) {
    constexpr int KP = K + 4;
    #pragma unroll
    for (int i = 0; i < K * 64 / 256; i++) {
        int idx = t + i * 256;
        int k = idx >> 6, nn = idx & 63;
        wsT[nn * KP + k] = to_tf32(w[idx]);
    }
}

// warp MMA mainloop: 16 rows (rbase..rbase+15) x 64 cols, acc[8][4]
template <int K>
__device__ __forceinline__ void warp_mma(float (&acc)[8][4], const float* xs, const float* wsT,
                                         int rbase, int g, int tig) {
    constexpr int KP = K + 4;
    const float* xr0 = xs + (rbase + g) * KP;
    const float* xr1 = xs + (rbase + g + 8) * KP;
    #pragma unroll
    for (int ks = 0; ks < K / 8; ks++) {
        int k0 = ks * 8;
        uint32_t a[4];
        a[0] = __float_as_uint(xr0[k0 + tig]);
        a[1] = __float_as_uint(xr1[k0 + tig]);
        a[2] = __float_as_uint(xr0[k0 + tig + 4]);
        a[3] = __float_as_uint(xr1[k0 + tig + 4]);
        #pragma unroll
        for (int nt = 0; nt < 8; nt++) {
            const float* wr = wsT + (nt * 8 + g) * KP;
            uint32_t b[2];
            b[0] = __float_as_uint(wr[k0 + tig]);
            b[1] = __float_as_uint(wr[k0 + 4 + tig]);
            mma_tf32(acc[nt], a, b);
        }
    }
}

// epilogue: add bias/rowbias, optional stats, store to y[n,64]
template <bool RB>
__device__ __forceinline__ void mma_epilogue(float (&acc)[8][4], int node0, int rbase,
                                             int g, int tig, int lane,
                                             const float* __restrict__ bias,
                                             const float* __restrict__ rowbias,
                                             float* __restrict__ y,
                                             float* csum, float* csq, int n) {
    int r0 = node0 + rbase + g;
    int r1 = r0 + 8;
    bool v0 = r0 < n, v1 = r1 < n;
    float ps[8][2], pq[8][2];
    #pragma unroll
    for (int nt = 0; nt < 8; nt++) {
        int c = nt * 8 + 2 * tig;
        float2 bb0, bb1;
        if (RB) {
            bb0 = v0 ? *(const float2*)(rowbias + (size_t)r0 * 64 + c) : make_float2(0.f, 0.f);
            bb1 = v1 ? *(const float2*)(rowbias + (size_t)r1 * 64 + c) : make_float2(0.f, 0.f);
        } else {
            bb0 = *(const float2*)(bias + c);
            bb1 = bb0;
        }
        float v00 = acc[nt][0] + bb0.x, v01 = acc[nt][1] + bb0.y;
        float v10 = acc[nt][2] + bb1.x, v11 = acc[nt][3] + bb1.y;
        float s0 = 0.f, s1 = 0.f, q0 = 0.f, q1 = 0.f;
        if (v0) { s0 += v00; s1 += v01; q0 += v00 * v00; q1 += v01 * v01; }
        if (v1) { s0 += v10; s1 += v11; q0 += v10 * v10; q1 += v11 * v11; }
        ps[nt][0] = s0; ps[nt][1] = s1; pq[nt][0] = q0; pq[nt][1] = q1;
        if (v0) *(float2*)(y + (size_t)r0 * 64 + c) = make_float2(v00, v01);
        if (v1) *(float2*)(y + (size_t)r1 * 64 + c) = make_float2(v10, v11);
    }
    // reduce over groupID (lanes differing in bits 2..4)
    #pragma unroll
    for (int o = 4; o <= 16; o <<= 1) {
        #pragma unroll
        for (int nt = 0; nt < 8; nt++) {
            ps[nt][0] += __shfl_xor_sync(0xffffffffu, ps[nt][0], o);
            ps[nt][1] += __shfl_xor_sync(0xffffffffu, ps[nt][1], o);
            pq[nt][0] += __shfl_xor_sync(0xffffffffu, pq[nt][0], o);
            pq[nt][1] += __shfl_xor_sync(0xffffffffu, pq[nt][1], o);
        }
    }
    if (lane < 4) {
        #pragma unroll
        for (int nt = 0; nt < 8; nt++) {
            int c = nt * 8 + 2 * tig;
            atomicAdd(&csum[c], ps[nt][0]);
            atomicAdd(&csum[c + 1], ps[nt][1]);
            atomicAdd(&csq[c], pq[nt][0]);
            atomicAdd(&csq[c + 1], pq[nt][1]);
        }
    }
}

// ---------------- MMA GEMM kernel: y[128-tile,64] = x[tile,K] @ w[K,64] + bias/rowbias ----------------
template <int K, bool RB>
__global__ void __launch_bounds__(256, 2)
mmagemm_kernel(const float* __restrict__ x, const float* __restrict__ w,
               const float* __restrict__ bias, const float* __restrict__ rowbias,
               float* __restrict__ y,
               float* __restrict__ gsum, float* __restrict__ gsq, int n) {
    constexpr int KP = K + 4;
    extern __shared__ float sm[];
    float* xs  = sm;                 // 128 * KP
    float* wsT = sm + 128 * KP;      // 64 * KP
    __shared__ float csum[64], csq[64];

    const int t = threadIdx.x;
    const int lane = t & 31, warp = t >> 5;
    const int g = lane >> 2, tig = lane & 3;
    const int rbase = warp * 16;
    const int node0 = blockIdx.x * 128;

    if (t < 64) { csum[t] = 0.f; csq[t] = 0.f; }
    loadA_mma<K>(xs, x, node0, n, t);
    loadB_mma<K>(wsT, w, t);
    __syncthreads();

    float acc[8][4];
    #pragma unroll
    for (int nt = 0; nt < 8; nt++)
        #pragma unroll
        for (int j = 0; j < 4; j++) acc[nt][j] = 0.f;

    warp_mma<K>(acc, xs, wsT, rbase, g, tig);
    mma_epilogue<RB>(acc, node0, rbase, g, tig, lane, bias, rowbias, y, csum, csq, n);

    __syncthreads();
    if (t < 64) {
        atomicAdd(&gsum[t], csum[t]);
        atomicAdd(&gsq[t], csq[t]);
    }
}

// ---------------- fused layer-1 MLP (MMA): y = lrelu(x@w1+b1)@w2+b2, stats ----------------
__global__ void __launch_bounds__(256, 2)
mmamlp1_kernel(const float* __restrict__ x,
               const float* __restrict__ w1, const float* __restrict__ b1,
               const float* __restrict__ w2, const float* __restrict__ b2,
               float* __restrict__ y,
               float* __restrict__ gsum, float* __restrict__ gsq, int n) {
    constexpr int K = 64, KP = K + 4;
    extern __shared__ float sm[];
    float* xs   = sm;                  // 128 * KP (reused for hidden)
    float* ws1T = sm + 128 * KP;       // 64 * KP
    float* ws2T = ws1T + 64 * KP;      // 64 * KP
    __shared__ float csum[64], csq[64];

    const int t = threadIdx.x;
    const int lane = t & 31, warp = t >> 5;
    const int g = lane >> 2, tig = lane & 3;
    const int rbase = warp * 16;
    const int node0 = blockIdx.x * 128;

    if (t < 64) { csum[t] = 0.f; csq[t] = 0.f; }
    loadA_mma<K>(xs, x, node0, n, t);
    loadB_mma<K>(ws1T, w1, t);
    loadB_mma<K>(ws2T, w2, t);
    __syncthreads();

    float acc[8][4];
    #pragma unroll
    for (int nt = 0; nt < 8; nt++)
        #pragma unroll
        for (int j = 0; j < 4; j++) acc[nt][j] = 0.f;

    // stage 1: hidden = lrelu(x @ w1 + b1) — written back to this warp's own xs rows
    warp_mma<K>(acc, xs, ws1T, rbase, g, tig);
    __syncwarp();
    {
        float* xr0 = xs + (rbase + g) * KP;
        float* xr1 = xs + (rbase + g + 8) * KP;
        #pragma unroll
        for (int nt = 0; nt < 8; nt++) {
            int c = nt * 8 + 2 * tig;
            float2 bb = *(const float2*)(b1 + c);
            xr0[c]     = to_tf32(lrelu(acc[nt][0] + bb.x));
            xr0[c + 1] = to_tf32(lrelu(acc[nt][1] + bb.y));
            xr1[c]     = to_tf32(lrelu(acc[nt][2] + bb.x));
            xr1[c + 1] = to_tf32(lrelu(acc[nt][3] + bb.y));
        }
    }
    __syncwarp();

    #pragma unroll
    for (int nt = 0; nt < 8; nt++)
        #pragma unroll
        for (int j = 0; j < 4; j++) acc[nt][j] = 0.f;

    // stage 2: y = hidden @ w2 + b2 (reads only this warp's own rows)
    warp_mma<K>(acc, xs, ws2T, rbase, g, tig);
    mma_epilogue<false>(acc, node0, rbase, g, tig, lane, b2, nullptr, y, csum, csq, n);

    __syncthreads();
    if (t < 64) {
        atomicAdd(&gsum[t], csum[t]);
        atomicAdd(&gsq[t], csq[t]);
    }
}

// ---------------- BN apply + lrelu ----------------
__global__ void bnapply_kernel(const float* __restrict__ y,
                               const float* __restrict__ gsum, const float* __restrict__ gsq,
                               const float* __restrict__ g, const float* __restrict__ b,
                               float* __restrict__ out, int ldo, int off, int n) {
    __shared__ float sc[64], sh[64];
    int t = threadIdx.x;
    if (t < 64) {
        float invn = 1.0f / (float)n;
        float m = gsum[t] * invn;
        float var = gsq[t] * invn - m * m;
        float s = g[t] * rsqrtf(var + 1e-5f);
        sc[t] = s; sh[t] = b[t] - m * s;
    }
    __syncthreads();
    int idx = blockIdx.x * blockDim.x + t;
    int i = idx >> 4, c = idx & 15;
    if (i >= n) return;
    float4 v = ((const float4*)y)[(size_t)i * 16 + c];
    v.x = lrelu(v.x * sc[c * 4 + 0] + sh[c * 4 + 0]);
    v.y = lrelu(v.y * sc[c * 4 + 1] + sh[c * 4 + 1]);
    v.z = lrelu(v.z * sc[c * 4 + 2] + sh[c * 4 + 2]);
    v.w = lrelu(v.w * sc[c * 4 + 3] + sh[c * 4 + 3]);
    ((float4*)(out + (size_t)i * ldo + off))[c] = v;
}

// ---------------- head: lrelu(bn(y)) @ fc_w2 + b2 -> sigmoid ----------------
__global__ void head_kernel(const float* __restrict__ y,
                            const float* __restrict__ gsum, const float* __restrict__ gsq,
                            const float* __restrict__ g, const float* __restrict__ b,
                            const float* __restrict__ w2, const float* __restrict__ b2,
                            float* __restrict__ out, int n) {
    __shared__ float sc[64], sh[64];
    int t = threadIdx.x;
    if (t < 64) {
        float invn = 1.0f / (float)n;
        float m = gsum[t] * invn;
        float var = gsq[t] * invn - m * m;
        float s = g[t] * rsqrtf(var + 1e-5f);
        sc[t] = s; sh[t] = b[t] - m * s;
    }
    __syncthreads();
    int lane = t & 31;
    int i = (blockIdx.x * blockDim.x + t) >> 5;
    if (i >= n) return;
    float2 v = ((const float2*)y)[(size_t)i * 32 + lane];
    float z0 = lrelu(v.x * sc[2 * lane] + sh[2 * lane]);
    float z1 = lrelu(v.y * sc[2 * lane + 1] + sh[2 * lane + 1]);
    float a = z0 * w2[2 * lane] + z1 * w2[2 * lane + 1];
    #pragma unroll
    for (int o = 16; o; o >>= 1) a += __shfl_xor_sync(0xffffffffu, a, o);
    if (lane == 0) out[i] = 1.0f / (1.0f + expf(-(a + b2[0])));
}

// ---------------- launch ----------------
extern "C" void kernel_launch(void* const* d_in, const int* in_sizes, int n_in,
                              void* d_out, int out_size) {
    const int*   node_deg = (const int*)d_in[0];
    const int*   node_lab = (const int*)d_in[1];
    const int*   edge     = (const int*)d_in[2];
    const float* emb_deg  = (const float*)d_in[3];
    const float* emb_lab  = (const float*)d_in[4];
    const float* l0_w1 = (const float*)d_in[5];
    const float* l0_b1 = (const float*)d_in[6];
    const float* l0_w2 = (const float*)d_in[7];
    const float* l0_b2 = (const float*)d_in[8];
    const float* l0_eps = (const float*)d_in[9];
    const float* bn0_g = (const float*)d_in[10];
    const float* bn0_b = (const float*)d_in[11];
    const float* l1_w1 = (const float*)d_in[12];
    const float* l1_b1 = (const float*)d_in[13];
    const float* l1_w2 = (const float*)d_in[14];
    const float* l1_b2 = (const float*)d_in[15];
    const float* l1_eps = (const float*)d_in[16];
    const float* bn1_g = (const float*)d_in[17];
    const float* bn1_b = (const float*)d_in[18];
    const float* fc_w1 = (const float*)d_in[19];
    const float* fc_b1 = (const float*)d_in[20];
    const float* fc_bn_g = (const float*)d_in[21];
    const float* fc_bn_b = (const float*)d_in[22];
    const float* fc_w2 = (const float*)d_in[23];
    const float* fc_b2 = (const float*)d_in[24];

    int n = in_sizes[0];
    int E = in_sizes[2] / 2;

    float *XC, *agg, *ybuf, *hb, *sumv, *sqv;
    cudaGetSymbolAddress((void**)&XC,   d_XC);
    cudaGetSymbolAddress((void**)&agg,  d_agg);
    cudaGetSymbolAddress((void**)&ybuf, d_ybuf);
    cudaGetSymbolAddress((void**)&hb,   d_hb);
    cudaGetSymbolAddress((void**)&sumv, d_sum);
    cudaGetSymbolAddress((void**)&sqv,  d_sq);

    const int SMEM_GEMM128 = (128 + 64) * (128 + 4) * 4;       // 101376
    const int SMEM_MLP     = (128 + 64 + 64) * (64 + 4) * 4;   // 69632
    cudaFuncSetAttribute(mmagemm_kernel<128, false>, cudaFuncAttributeMaxDynamicSharedMemorySize, SMEM_GEMM128);
    cudaFuncSetAttribute(mmagemm_kernel<128, true>,  cudaFuncAttributeMaxDynamicSharedMemorySize, SMEM_GEMM128);
    cudaFuncSetAttribute(mmamlp1_kernel,             cudaFuncAttributeMaxDynamicSharedMemorySize, SMEM_MLP);

    int NB = (n + 1023) / 1024;
    int NT = (n + 127) / 128;

    // init + tables + head rowbias + CSR build
    zero_kernel<<<(n + 255) / 256, 256>>>(node_deg, node_lab, n);
    tables_kernel<<<162, 128>>>(emb_deg, emb_lab, l0_w1, fc_w1);
    hb_kernel<<<((size_t)n * 16 + 255) / 256, 256>>>(fc_b1, n);
    count_kernel<<<(E + 255) / 256, 256>>>(edge, E);
    scanA_kernel<<<NB, 1024>>>(n);
    scanB_kernel<<<1, 32>>>(NB, n);
    scanC_kernel<<<NB, 1024>>>(n);
    fill_kernel<<<(E + 255) / 256, 256>>>(edge, E);

    // ---- GIN layer 0 (dictionary gather): z1 -> agg; y = z1 @ w2 + b2 ----
    gather0_kernel<<<(n + 255) / 256, 256>>>(l0_eps, l0_b1, n);
    mmagemm_kernel<128, false><<<NT, 256, SMEM_GEMM128>>>(agg, l0_w2, l0_b2, nullptr, ybuf, sumv + 0, sqv + 0, n);
    bnapply_kernel<<<((size_t)n * 16 + 255) / 256, 256>>>(ybuf, sumv + 0, sqv + 0, bn0_g, bn0_b, XC, 128, 0, n);

    // ---- GIN layer 1: gather + fused MLP (MMA) ----
    gather1_kernel<<<((size_t)((n + 1) / 2) * 32 + 255) / 256, 256>>>(XC, 128, l1_eps, n);
    mmamlp1_kernel<<<NT, 256, SMEM_MLP>>>(agg, l1_w1, l1_b1, l1_w2, l1_b2, ybuf, sumv + 64, sqv + 64, n);
    bnapply_kernel<<<((size_t)n * 16 + 255) / 256, 256>>>(ybuf, sumv + 64, sqv + 64, bn1_g, bn1_b, XC, 128, 64, n);

    // ---- head (h0 part folded into hb): y = [h1|h2] @ fc_w1[128:256] + hb ----
    mmagemm_kernel<128, true><<<NT, 256, SMEM_GEMM128>>>(XC, fc_w1 + 128 * 64, nullptr, hb, ybuf, sumv + 128, sqv + 128, n);
    head_kernel<<<((size_t)n * 32 + 255) / 256, 256>>>(ybuf, sumv + 128, sqv + 128, fc_bn_g, fc_bn_b, fc_w2, fc_b2, (float*)d_out, n);
}